// round 5
// baseline (speedup 1.0000x reference)
#include <cuda_runtime.h>
#include <cstdint>

// DistEmb forward: out[i, :] = table[idx[i], :]
// table: [2e6, 128] fp32 (1 GB), idx: [1,048,576] int32, out: 512 MB fp32.
//
// R5 strategy: bucket-sort the 1M row-ids by table index (2048 buckets,
// 1024 rows / 512KB of table each), then gather in sorted order.
//  - duplicate ids become temporally adjacent -> L2/L1 hits (read traffic
//    512MB -> ~403MB distinct-rows minimum)
//  - table reads sweep the table in ascending order -> DRAM row locality
//  - output stores become permuted but each row is still one contiguous,
//    fully-coalesced 512B burst (streaming __stcs, evict-first)
// Sort passes (~25MB, mostly L2) cost a few us. All scratch is __device__
// global; everything is recomputed on every call (graph-replay safe), and
// d_out content is independent of intra-bucket atomic ordering.

static constexpr int EMB_F4       = 32;       // 128 floats = 32 float4
static constexpr int NBUCKETS     = 2048;
static constexpr int BUCKET_SHIFT = 10;       // bucket = src >> 10 (2e6/1024 = 1954 buckets used)
static constexpr int MAX_IDS      = 1 << 20;  // 1,048,576
static constexpr int THREADS      = 256;
static constexpr int ROWS_PER_WARP = 4;

__device__ int g_count[NBUCKETS];
__device__ int g_offset[NBUCKETS];
__device__ int g_perm[MAX_IDS];

// ---- pass 1: zero bucket counters -----------------------------------------
__global__ void k_zero()
{
    int i = blockIdx.x * blockDim.x + threadIdx.x;
    if (i < NBUCKETS) g_count[i] = 0;
}

// ---- pass 2: histogram (smem-privatized) ----------------------------------
__global__ __launch_bounds__(THREADS)
void k_hist(const int* __restrict__ idx, int n)
{
    __shared__ int sh[NBUCKETS];
    for (int i = threadIdx.x; i < NBUCKETS; i += THREADS) sh[i] = 0;
    __syncthreads();
    for (int i = blockIdx.x * THREADS + threadIdx.x; i < n;
         i += gridDim.x * THREADS)
        atomicAdd(&sh[__ldg(&idx[i]) >> BUCKET_SHIFT], 1);
    __syncthreads();
    for (int i = threadIdx.x; i < NBUCKETS; i += THREADS) {
        int c = sh[i];
        if (c) atomicAdd(&g_count[i], c);
    }
}

// ---- pass 3: exclusive scan of 2048 counters (one block, 1024 threads) ----
__global__ __launch_bounds__(1024)
void k_scan()
{
    __shared__ int buf[1024];
    const int t = threadIdx.x;
    const int a = g_count[2 * t];
    const int b = g_count[2 * t + 1];
    const int s = a + b;
    buf[t] = s;
    __syncthreads();
    // Hillis-Steele inclusive scan over the 1024 pair-sums
    for (int d = 1; d < 1024; d <<= 1) {
        int v = (t >= d) ? buf[t - d] : 0;
        __syncthreads();
        buf[t] += v;
        __syncthreads();
    }
    const int excl = buf[t] - s;        // exclusive prefix for this pair
    g_offset[2 * t]     = excl;
    g_offset[2 * t + 1] = excl + a;
}

// ---- pass 4: scatter permutation ------------------------------------------
__global__ __launch_bounds__(THREADS)
void k_scatter(const int* __restrict__ idx, int n)
{
    for (int i = blockIdx.x * THREADS + threadIdx.x; i < n;
         i += gridDim.x * THREADS) {
        const int b = __ldg(&idx[i]) >> BUCKET_SHIFT;
        const int pos = atomicAdd(&g_offset[b], 1);
        g_perm[pos] = i;
    }
}

// ---- pass 5: gather in sorted order ---------------------------------------
__global__ __launch_bounds__(THREADS)
void k_gather_sorted(const float4* __restrict__ table,
                     const int* __restrict__ idx,
                     float4* __restrict__ out,
                     int num_ids)
{
    const int gwarp = (blockIdx.x * THREADS + threadIdx.x) >> 5;
    const int lane  = threadIdx.x & 31;
    const int slot0 = gwarp * ROWS_PER_WARP;
    if (slot0 >= num_ids) return;

    if (slot0 + ROWS_PER_WARP <= num_ids) {
        int p[ROWS_PER_WARP], src[ROWS_PER_WARP];
#pragma unroll
        for (int r = 0; r < ROWS_PER_WARP; r++)
            p[r] = __ldg(&g_perm[slot0 + r]);       // warp-uniform
#pragma unroll
        for (int r = 0; r < ROWS_PER_WARP; r++)
            src[r] = __ldg(&idx[p[r]]);             // L2-resident (4MB buf)

        float4 v[ROWS_PER_WARP];
#pragma unroll
        for (int r = 0; r < ROWS_PER_WARP; r++)     // 4 independent LDG.128
            v[r] = __ldg(&table[(size_t)src[r] * EMB_F4 + lane]);
#pragma unroll
        for (int r = 0; r < ROWS_PER_WARP; r++)     // streaming 512B bursts
            __stcs(&out[(size_t)p[r] * EMB_F4 + lane], v[r]);
    } else {
        for (int r = 0; slot0 + r < num_ids; r++) {
            const int p = __ldg(&g_perm[slot0 + r]);
            const int src = __ldg(&idx[p]);
            float4 v = __ldg(&table[(size_t)src * EMB_F4 + lane]);
            __stcs(&out[(size_t)p * EMB_F4 + lane], v);
        }
    }
}

// ---- fallback (unsorted, R4 kernel) for unexpected sizes ------------------
__global__ __launch_bounds__(THREADS)
void k_gather_plain(const float4* __restrict__ table,
                    const int* __restrict__ idx,
                    float4* __restrict__ out,
                    int num_ids)
{
    const int gwarp = (blockIdx.x * THREADS + threadIdx.x) >> 5;
    const int lane  = threadIdx.x & 31;
    const int row0  = gwarp * ROWS_PER_WARP;
    if (row0 >= num_ids) return;
    for (int r = 0; r < ROWS_PER_WARP && row0 + r < num_ids; r++) {
        const int src = __ldg(&idx[row0 + r]);
        float4 v = __ldg(&table[(size_t)src * EMB_F4 + lane]);
        __stcs(&out[(size_t)(row0 + r) * EMB_F4 + lane], v);
    }
}

extern "C" void kernel_launch(void* const* d_in, const int* in_sizes, int n_in,
                              void* d_out, int out_size)
{
    // Identify inputs by element count (table: 268,435,456 elems; idx: 1,048,576)
    const void* table_p = d_in[0];
    const void* idx_p   = d_in[1];
    int         idx_n   = in_sizes[1];
    if (n_in >= 2 && in_sizes[0] < in_sizes[1]) {
        table_p = d_in[1];
        idx_p   = d_in[0];
        idx_n   = in_sizes[0];
    }

    const float4* table = (const float4*)table_p;
    const int*    idx   = (const int*)idx_p;
    float4*       out   = (float4*)d_out;

    const int rows_per_block = (THREADS / 32) * ROWS_PER_WARP;      // 32
    const int gather_grid = (idx_n + rows_per_block - 1) / rows_per_block;

    if (idx_n > MAX_IDS) {  // scratch too small — direct gather
        k_gather_plain<<<gather_grid, THREADS>>>(table, idx, out, idx_n);
        return;
    }

    const int pass_grid = 1024;   // grid-stride histogram/scatter

    k_zero<<<(NBUCKETS + 255) / 256, 256>>>();
    k_hist<<<pass_grid, THREADS>>>(idx, idx_n);
    k_scan<<<1, 1024>>>();
    k_scatter<<<pass_grid, THREADS>>>(idx, idx_n);
    k_gather_sorted<<<gather_grid, THREADS>>>(table, idx, out, idx_n);
}

// round 6
// speedup vs baseline: 1.3748x; 1.3748x over previous
#include <cuda_runtime.h>
#include <cstdint>

// DistEmb forward: out[i, :] = table[idx[i], :]
// table: [2e6, 128] fp32 (1 GB), idx: [1,048,576] int32, out: 512 MB fp32.
//
// R6: R4 architecture (warp-per-row, float4/lane, __stcs streaming stores)
// with ROWS_PER_WARP raised 4 -> 8: 8 warp-uniform idx loads, then 8
// independent 16B gathers per lane batched ahead of 8 streaming stores.
// Deeper MLP fills the DRAM queues harder; store stream stays evict-first
// so it does not displace gathered table rows from L2 (~26% of gathers are
// duplicate rows; L2 captures a slice of them).

static constexpr int EMB_F4        = 32;  // 128 floats = 32 float4
static constexpr int THREADS       = 256; // 8 warps / block
static constexpr int ROWS_PER_WARP = 8;

__global__ __launch_bounds__(THREADS)
void distemb_gather_kernel(const float4* __restrict__ table,
                           const int* __restrict__ idx,
                           float4* __restrict__ out,
                           int num_ids)
{
    const int gwarp = (blockIdx.x * THREADS + threadIdx.x) >> 5;
    const int lane  = threadIdx.x & 31;
    const int row0  = gwarp * ROWS_PER_WARP;
    if (row0 >= num_ids) return;

    if (row0 + ROWS_PER_WARP <= num_ids) {
        // Fast path: 8 rows, loads fully batched before stores.
        int src[ROWS_PER_WARP];
#pragma unroll
        for (int r = 0; r < ROWS_PER_WARP; r++)
            src[r] = __ldg(&idx[row0 + r]);        // warp-uniform broadcasts

        float4 v[ROWS_PER_WARP];
#pragma unroll
        for (int r = 0; r < ROWS_PER_WARP; r++)    // 8 independent LDG.128
            v[r] = __ldg(&table[(size_t)src[r] * EMB_F4 + lane]);

#pragma unroll
        for (int r = 0; r < ROWS_PER_WARP; r++)    // streaming, evict-first
            __stcs(&out[(size_t)(row0 + r) * EMB_F4 + lane], v[r]);
    } else {
        for (int r = 0; row0 + r < num_ids; r++) {
            const int src = __ldg(&idx[row0 + r]);
            float4 v = __ldg(&table[(size_t)src * EMB_F4 + lane]);
            __stcs(&out[(size_t)(row0 + r) * EMB_F4 + lane], v);
        }
    }
}

extern "C" void kernel_launch(void* const* d_in, const int* in_sizes, int n_in,
                              void* d_out, int out_size)
{
    // Identify inputs by element count (table: 268,435,456 elems; idx: 1,048,576).
    const void* table_p = d_in[0];
    const void* idx_p   = d_in[1];
    int         idx_n   = in_sizes[1];
    if (n_in >= 2 && in_sizes[0] < in_sizes[1]) {
        table_p = d_in[1];
        idx_p   = d_in[0];
        idx_n   = in_sizes[0];
    }

    const float4* table = (const float4*)table_p;
    const int*    idx   = (const int*)idx_p;
    float4*       out   = (float4*)d_out;

    const int rows_per_block = (THREADS / 32) * ROWS_PER_WARP;  // 64
    const int grid = (idx_n + rows_per_block - 1) / rows_per_block;

    distemb_gather_kernel<<<grid, THREADS>>>(table, idx, out, idx_n);
}